// round 3
// baseline (speedup 1.0000x reference)
#include <cuda_runtime.h>
#include <cuda_bf16.h>

#define B_ 32
#define T_ 2048
#define V_ 128
#define S_ 256
#define L_ 513            // 2*S+1
#define NEGV -1e30f

// Scratch (no allocations allowed in kernel_launch)
__device__ float g_denom[B_ * T_];   // log-softmax denominator per (b,t)
__device__ float g_loss[B_];         // per-batch normalized loss

// ---------------------------------------------------------------------------
// Kernel 1: denom[b,t] = max_v x + log(sum_v exp(x - max))   (warp per row)
// ---------------------------------------------------------------------------
__global__ __launch_bounds__(128) void k_denom(const float* __restrict__ pred) {
    int row  = blockIdx.x * 4 + (threadIdx.x >> 5);
    int lane = threadIdx.x & 31;
    const float4* p = reinterpret_cast<const float4*>(pred) + (size_t)row * (V_ / 4);
    float4 v = p[lane];
    float m = fmaxf(fmaxf(v.x, v.y), fmaxf(v.z, v.w));
#pragma unroll
    for (int o = 16; o; o >>= 1) m = fmaxf(m, __shfl_xor_sync(0xffffffffu, m, o));
    float s = __expf(v.x - m) + __expf(v.y - m) + __expf(v.z - m) + __expf(v.w - m);
#pragma unroll
    for (int o = 16; o; o >>= 1) s += __shfl_xor_sync(0xffffffffu, s, o);
    if (lane == 0) g_denom[row] = m + __logf(s);
}

// ---------------------------------------------------------------------------
// Kernel 2: CTC forward DP, one CTA per batch element, log domain.
// alpha stored in shared, double-buffered, index shifted by +2 so that
// a1 = buf[s+2], a2 = buf[s+1], a3 = buf[s] with buf[0..1] = NEG pads.
// ---------------------------------------------------------------------------
__global__ __launch_bounds__(256) void k_dp(const float* __restrict__ pred,
                                            const int*   __restrict__ plen,
                                            const int*   __restrict__ gt,
                                            const int*   __restrict__ glen) {
    int b   = blockIdx.x;
    int tid = threadIdx.x;
    const float* P   = pred + (size_t)b * T_ * V_;
    const float* D   = g_denom + b * T_;
    const int*   lab = gt + b * S_;
    int il = plen[b];
    int tl = glen[b];

    __shared__ float rowbuf[2][V_];
    __shared__ float abuf[2][L_ + 3];   // [s+2], pads at [0],[1]

    // Per-thread extended-label setup: s0 = tid, s1 = tid+256 (tid 0 also s=512).
    // even s -> blank(0), no skip; odd s=2i+1 -> lab[i], skip iff i>=1 && lab[i]!=lab[i-1]
    int e0, e1; bool sk0, sk1;
    {
        int s = tid;
        if (s & 1) { int i = s >> 1; e0 = lab[i]; sk0 = (i >= 1) && (lab[i] != lab[i - 1]); }
        else       { e0 = 0; sk0 = false; }
        s = tid + 256;
        if (s & 1) { int i = s >> 1; e1 = lab[i]; sk1 = (lab[i] != lab[i - 1]); }
        else       { e1 = 0; sk1 = false; }
    }

    // Initialize alpha0 to NEG everywhere (both buffers' pads too)
    for (int i = tid; i < L_ + 3; i += 256) abuf[0][i] = NEGV;
    if (tid < 2) abuf[1][tid] = NEGV;
    // Prefetch row t=1
    float pf = 0.0f;
    if (tid < V_ && il > 1) pf = P[V_ + tid];
    __syncthreads();

    if (tid < V_) rowbuf[1][tid] = pf;
    if (tid == 0) abuf[0][2] = P[0]      - D[0];   // s=0: blank at t=0
    if (tid == 1) abuf[0][3] = P[lab[0]] - D[0];   // s=1: first label at t=0
    __syncthreads();

    int cur  = 0;
    float dt = D[1];                                // denom for t=1 (only used if il>1)

    for (int t = 1; t < il; t++) {
        int nxt = cur ^ 1;
        const float* rb = rowbuf[t & 1];

        // Prefetch row t+1 and denom t+1
        float pfn = 0.0f, dn = dt;
        if (t + 1 < T_) {
            if (tid < V_) pfn = P[(size_t)(t + 1) * V_ + tid];
            dn = D[t + 1];
        }

        const float* ap = abuf[cur];
        float*       an = abuf[nxt];

        // element s0 = tid
        {
            float a1 = ap[tid + 2];
            float a2 = ap[tid + 1];
            float a3 = sk0 ? ap[tid] : NEGV;
            float m  = fmaxf(a1, fmaxf(a2, a3));
            float sm = __expf(a1 - m) + __expf(a2 - m) + __expf(a3 - m);
            an[tid + 2] = m + __logf(sm) + (rb[e0] - dt);
        }
        // element s1 = tid + 256
        {
            int s = tid + 256;
            float a1 = ap[s + 2];
            float a2 = ap[s + 1];
            float a3 = sk1 ? ap[s] : NEGV;
            float m  = fmaxf(a1, fmaxf(a2, a3));
            float sm = __expf(a1 - m) + __expf(a2 - m) + __expf(a3 - m);
            an[s + 2] = m + __logf(sm) + (rb[e1] - dt);
        }
        // element s = 512 (even, blank, no skip) handled by thread 0
        if (tid == 0) {
            float a1 = ap[512 + 2];
            float a2 = ap[512 + 1];
            float m  = fmaxf(a1, a2);
            float sm = __expf(a1 - m) + __expf(a2 - m) + __expf(NEGV - m);
            an[512 + 2] = m + __logf(sm) + (rb[0] - dt);
        }

        // store prefetched next row into the other row slot
        if (tid < V_) rowbuf[(t + 1) & 1][tid] = pfn;
        dt = dn;
        __syncthreads();
        cur = nxt;
    }

    if (tid == 0) {
        int last = 2 * tl;
        float a = abuf[cur][last + 2];
        float c = abuf[cur][last + 1];
        float m = fmaxf(a, c);
        float lae = m + __logf(__expf(a - m) + __expf(c - m));
        float lo = -lae;
        if (!(lo < 1e10f)) lo = 0.0f;          // zero_infinity
        g_loss[b] = lo / (float)tl;
    }
}

// ---------------------------------------------------------------------------
// Kernel 3: deterministic mean over batch
// ---------------------------------------------------------------------------
__global__ void k_reduce(float* out) {
    float v = (threadIdx.x < B_) ? g_loss[threadIdx.x] : 0.0f;
#pragma unroll
    for (int o = 16; o; o >>= 1) v += __shfl_xor_sync(0xffffffffu, v, o);
    if (threadIdx.x == 0) out[0] = v / (float)B_;
}

// ---------------------------------------------------------------------------
extern "C" void kernel_launch(void* const* d_in, const int* in_sizes, int n_in,
                              void* d_out, int out_size) {
    const float* pred = (const float*)d_in[0];
    const int*   plen = (const int*)d_in[1];
    const int*   gt   = (const int*)d_in[2];
    const int*   glen = (const int*)d_in[3];

    k_denom<<<(B_ * T_) / 4, 128>>>(pred);
    k_dp<<<B_, 256>>>(pred, plen, gt, glen);
    k_reduce<<<1, 32>>>((float*)d_out);
}

// round 7
// speedup vs baseline: 1.5300x; 1.5300x over previous
#include <cuda_runtime.h>
#include <cuda_bf16.h>
#include <cstdint>

#define B_ 32
#define T_ 2048
#define V_ 128
#define S_ 256
#define L_ 513            // 2*S+1
#define NEGV -1e30f
#define LOG2E 1.4426950408889634f
#define LN2   0.6931471805599453f

// Scratch (no allocations allowed in kernel_launch)
__device__ float g_denom[B_ * T_];   // log-softmax denominator per (b,t)
__device__ float g_loss[B_];         // per-batch normalized loss

__device__ __forceinline__ float ex2(float x) {
    float y; asm("ex2.approx.ftz.f32 %0, %1;" : "=f"(y) : "f"(x)); return y;
}
__device__ __forceinline__ float lg2(float x) {
    float y; asm("lg2.approx.f32 %0, %1;" : "=f"(y) : "f"(x)); return y;
}

// ---------------------------------------------------------------------------
// Kernel 1: denom[b,t] = max_v x + log(sum_v exp(x - max))   (warp per row)
// ---------------------------------------------------------------------------
__global__ __launch_bounds__(128) void k_denom(const float* __restrict__ pred) {
    int row  = blockIdx.x * 4 + (threadIdx.x >> 5);
    int lane = threadIdx.x & 31;
    const float4* p = reinterpret_cast<const float4*>(pred) + (size_t)row * (V_ / 4);
    float4 v = p[lane];
    float m = fmaxf(fmaxf(v.x, v.y), fmaxf(v.z, v.w));
#pragma unroll
    for (int o = 16; o; o >>= 1) m = fmaxf(m, __shfl_xor_sync(0xffffffffu, m, o));
    float s = __expf(v.x - m) + __expf(v.y - m) + __expf(v.z - m) + __expf(v.w - m);
#pragma unroll
    for (int o = 16; o; o >>= 1) s += __shfl_xor_sync(0xffffffffu, s, o);
    if (lane == 0) g_denom[row] = m + __logf(s);
}

// ---------------------------------------------------------------------------
// Kernel 2: CTC forward DP, one CTA per batch element, log2 domain.
// cp.async 4-deep pipeline for prediction rows; denominators preloaded to smem.
// alpha double-buffered in shared, shifted +2: a1=buf[s+2], a2=buf[s+1], a3=buf[s].
// ---------------------------------------------------------------------------
__global__ __launch_bounds__(256) void k_dp(const float* __restrict__ pred,
                                            const int*   __restrict__ plen,
                                            const int*   __restrict__ gt,
                                            const int*   __restrict__ glen) {
    int b   = blockIdx.x;
    int tid = threadIdx.x;
    const float* P   = pred + (size_t)b * T_ * V_;
    const int*   lab = gt + b * S_;
    int il = plen[b];
    int tl = glen[b];

    __shared__ float rowbuf[5][V_];     // 5-stage ring, stage = t mod 5
    __shared__ float abuf[2][L_ + 3];   // [s+2], pads at [0],[1]
    __shared__ float sden[T_];          // denom * LOG2E

    // Preload all denominators (scaled to log2 domain)
    {
        const float* D = g_denom + b * T_;
#pragma unroll
        for (int i = 0; i < T_ / 256; i++)
            sden[i * 256 + tid] = D[i * 256 + tid] * LOG2E;
    }

    // Per-thread extended-label setup: s0 = tid, s1 = tid+256 (tid 0 also s=512).
    int e0, e1; bool sk0, sk1;
    {
        int s = tid;
        if (s & 1) { int i = s >> 1; e0 = lab[i]; sk0 = (i >= 1) && (lab[i] != lab[i - 1]); }
        else       { e0 = 0; sk0 = false; }
        s = tid + 256;
        if (s & 1) { int i = s >> 1; e1 = lab[i]; sk1 = (lab[i] != lab[i - 1]); }
        else       { e1 = 0; sk1 = false; }
    }

    // Initialize alpha0 to NEG everywhere (both buffers' pads too)
    for (int i = tid; i < L_ + 3; i += 256) abuf[0][i] = NEGV;
    if (tid < 2) abuf[1][tid] = NEGV;

    // cp.async prologue: rows 1..4 into stages 1..4 (4 groups in flight)
#pragma unroll
    for (int r = 1; r <= 4; r++) {
        if (tid < 32 && r < T_) {
            unsigned int dst = (unsigned int)__cvta_generic_to_shared(&rowbuf[r % 5][tid * 4]);
            const float4* src = reinterpret_cast<const float4*>(P + (size_t)r * V_) + tid;
            asm volatile("cp.async.cg.shared.global [%0], [%1], 16;" :: "r"(dst), "l"(src));
        }
        asm volatile("cp.async.commit_group;");
    }

    __syncthreads();   // sden + NEG-fill visible

    if (tid == 0) abuf[0][2] = fmaf(P[0],      LOG2E, -sden[0]);   // s=0: blank at t=0
    if (tid == 1) abuf[0][3] = fmaf(P[lab[0]], LOG2E, -sden[0]);   // s=1: first label at t=0

    int cur = 0;
    int rs  = 1;   // read stage = t mod 5

    for (int t = 1; t < il; t++) {
        // row t landed (committed 4 groups ago; 3 newer remain in flight)
        asm volatile("cp.async.wait_group 3;");
        __syncthreads();   // publishes row t to all threads + prev alpha stores

        // issue prefetch of row t+4 into stage (t-1) mod 5 (dead after barrier)
        {
            int ws = rs == 0 ? 4 : rs - 1;
            int r  = t + 4;
            if (tid < 32 && r < T_) {
                unsigned int dst = (unsigned int)__cvta_generic_to_shared(&rowbuf[ws][tid * 4]);
                const float4* src = reinterpret_cast<const float4*>(P + (size_t)r * V_) + tid;
                asm volatile("cp.async.cg.shared.global [%0], [%1], 16;" :: "r"(dst), "l"(src));
            }
            asm volatile("cp.async.commit_group;");
        }

        const float* rb = rowbuf[rs];
        const float* ap = abuf[cur];
        float*       an = abuf[cur ^ 1];
        float dt2 = sden[t];
        float lp0 = fmaf(rb[e0], LOG2E, -dt2);
        float lp1 = fmaf(rb[e1], LOG2E, -dt2);

        // element s0 = tid
        {
            float a1 = ap[tid + 2];
            float a2 = ap[tid + 1];
            float a3 = sk0 ? ap[tid] : NEGV;
            float m  = fmaxf(a1, fmaxf(a2, a3));
            float sm = ex2(a1 - m) + ex2(a2 - m) + ex2(a3 - m);
            an[tid + 2] = m + lg2(sm) + lp0;
        }
        // element s1 = tid + 256
        {
            int s = tid + 256;
            float a1 = ap[s + 2];
            float a2 = ap[s + 1];
            float a3 = sk1 ? ap[s] : NEGV;
            float m  = fmaxf(a1, fmaxf(a2, a3));
            float sm = ex2(a1 - m) + ex2(a2 - m) + ex2(a3 - m);
            an[s + 2] = m + lg2(sm) + lp1;
        }
        // element s = 512 (even, blank, no skip) handled by thread 0
        if (tid == 0) {
            float a1 = ap[512 + 2];
            float a2 = ap[512 + 1];
            float m  = fmaxf(a1, a2);
            float sm = ex2(a1 - m) + ex2(a2 - m);
            float lpB = fmaf(rb[0], LOG2E, -dt2);
            an[512 + 2] = m + lg2(sm) + lpB;
        }

        rs = (rs == 4) ? 0 : rs + 1;
        cur ^= 1;
    }

    asm volatile("cp.async.wait_all;");
    __syncthreads();

    if (tid == 0) {
        int last = 2 * tl;
        float a = abuf[cur][last + 2];
        float c = abuf[cur][last + 1];
        float m = fmaxf(a, c);
        float lae2 = m + lg2(ex2(a - m) + ex2(c - m));
        float lo = -lae2 * LN2;
        if (!(lo < 1e10f)) lo = 0.0f;          // zero_infinity
        g_loss[b] = lo / (float)tl;
    }
}

// ---------------------------------------------------------------------------
// Kernel 3: deterministic mean over batch
// ---------------------------------------------------------------------------
__global__ void k_reduce(float* out) {
    float v = (threadIdx.x < B_) ? g_loss[threadIdx.x] : 0.0f;
#pragma unroll
    for (int o = 16; o; o >>= 1) v += __shfl_xor_sync(0xffffffffu, v, o);
    if (threadIdx.x == 0) out[0] = v / (float)B_;
}

// ---------------------------------------------------------------------------
extern "C" void kernel_launch(void* const* d_in, const int* in_sizes, int n_in,
                              void* d_out, int out_size) {
    const float* pred = (const float*)d_in[0];
    const int*   plen = (const int*)d_in[1];
    const int*   gt   = (const int*)d_in[2];
    const int*   glen = (const int*)d_in[3];

    k_denom<<<(B_ * T_) / 4, 128>>>(pred);
    k_dp<<<B_, 256>>>(pred, plen, gt, glen);
    k_reduce<<<1, 32>>>((float*)d_out);
}

// round 12
// speedup vs baseline: 1.6206x; 1.0592x over previous
#include <cuda_runtime.h>
#include <cuda_bf16.h>
#include <cstdint>

#define B_ 32
#define T_ 2048
#define V_ 128
#define S_ 256
#define L_ 513            // 2*S+1
#define NEGV -1e30f
#define LOG2E 1.4426950408889634f
#define LN2   0.6931471805599453f

// Scratch (no allocations allowed in kernel_launch)
__device__ float g_lp[B_ * T_ * V_];   // log2-softmax (32 MB)
__device__ float g_loss[B_];           // per-batch normalized loss

__device__ __forceinline__ float ex2(float x) {
    float y; asm("ex2.approx.ftz.f32 %0, %1;" : "=f"(y) : "f"(x)); return y;
}
__device__ __forceinline__ float lg2(float x) {
    float y; asm("lg2.approx.f32 %0, %1;" : "=f"(y) : "f"(x)); return y;
}

// ---------------------------------------------------------------------------
// Kernel 1: log2-softmax, warp per row: out = (v-m)*log2e - log2(sum 2^..)
// ---------------------------------------------------------------------------
__global__ __launch_bounds__(128) void k_lp(const float* __restrict__ pred) {
    int row  = blockIdx.x * 4 + (threadIdx.x >> 5);
    int lane = threadIdx.x & 31;
    const float4* p = reinterpret_cast<const float4*>(pred) + (size_t)row * (V_ / 4);
    float4 v = p[lane];
    float m = fmaxf(fmaxf(v.x, v.y), fmaxf(v.z, v.w));
#pragma unroll
    for (int o = 16; o; o >>= 1) m = fmaxf(m, __shfl_xor_sync(0xffffffffu, m, o));
    float wx = (v.x - m) * LOG2E, wy = (v.y - m) * LOG2E;
    float wz = (v.z - m) * LOG2E, ww = (v.w - m) * LOG2E;
    float s = ex2(wx) + ex2(wy) + ex2(wz) + ex2(ww);
#pragma unroll
    for (int o = 16; o; o >>= 1) s += __shfl_xor_sync(0xffffffffu, s, o);
    float l = lg2(s);
    float4 o4 = make_float4(wx - l, wy - l, wz - l, ww - l);
    reinterpret_cast<float4*>(g_lp)[(size_t)row * (V_ / 4) + lane] = o4;
}

// ---------------------------------------------------------------------------
// Kernel 2: CTC forward DP, one CTA (256 thr) per batch element, log2 domain.
// Thread tid owns even state s0=2*tid (blank, 2-term LSE) and odd s1=2*tid+1
// (label lab[tid], 3-term LSE with skip). Lane 255 also owns s=512.
// Alpha shifted +2 in shared: ap[x] = alpha(x-2); pads ap[0..1] = NEG.
// cp.async 4-deep pipeline streams log2-prob rows through a 5-stage ring.
// ---------------------------------------------------------------------------
__global__ __launch_bounds__(256) void k_dp(const int* __restrict__ plen,
                                            const int* __restrict__ gt,
                                            const int* __restrict__ glen) {
    int b   = blockIdx.x;
    int tid = threadIdx.x;
    const float* P   = g_lp + (size_t)b * T_ * V_;
    const int*   lab = gt + b * S_;
    int il = plen[b];
    int tl = glen[b];

    __shared__ __align__(16) float rowbuf[5][V_];     // 5-stage ring, stage = t mod 5
    __shared__ __align__(16) float abuf[2][L_ + 3];   // [s+2], pads at [0],[1]

    // Per-thread labels: odd state s1=2*tid+1 emits lab[tid]
    int s0   = 2 * tid;
    int eA   = lab[tid];
    bool skA = (tid >= 1) && (eA != lab[tid - 1]);
    bool has2 = (tid == 255);

    // Initialize alpha0 to NEG everywhere (both buffers' pads too)
    for (int i = tid; i < L_ + 3; i += 256) abuf[0][i] = NEGV;
    if (tid < 2) abuf[1][tid] = NEGV;

    // cp.async prologue: rows 1..4 into stages 1..4 (4 groups in flight)
#pragma unroll
    for (int r = 1; r <= 4; r++) {
        if (tid < 32 && r < T_) {
            unsigned int dst = (unsigned int)__cvta_generic_to_shared(&rowbuf[r % 5][tid * 4]);
            const float4* src = reinterpret_cast<const float4*>(P + (size_t)r * V_) + tid;
            asm volatile("cp.async.cg.shared.global [%0], [%1], 16;" :: "r"(dst), "l"(src));
        }
        asm volatile("cp.async.commit_group;");
    }

    __syncthreads();   // NEG-fill visible before planting

    if (tid == 0) abuf[0][2] = P[0];        // s=0: blank at t=0 (log2 prob)
    if (tid == 1) abuf[0][3] = P[lab[0]];   // s=1: first label at t=0

    int cur = 0;
    int rs  = 1;   // read stage = t mod 5

    for (int t = 1; t < il; t++) {
        asm volatile("cp.async.wait_group 3;");
        __syncthreads();   // publishes row t + alpha(t-1)

        // prefetch row t+4 into stage (t-1) mod 5 (dead after barrier)
        {
            int ws = (rs == 0) ? 4 : rs - 1;
            int r  = t + 4;
            if (tid < 32 && r < T_) {
                unsigned int dst = (unsigned int)__cvta_generic_to_shared(&rowbuf[ws][tid * 4]);
                const float4* src = reinterpret_cast<const float4*>(P + (size_t)r * V_) + tid;
                asm volatile("cp.async.cg.shared.global [%0], [%1], 16;" :: "r"(dst), "l"(src));
            }
            asm volatile("cp.async.commit_group;");
        }

        const float* rb = rowbuf[rs];
        const float* ap = abuf[cur];
        float*       an = abuf[cur ^ 1];

        float lpA = rb[eA];    // odd emission (random gather, issue early)
        float lpB = rb[0];     // blank emission (broadcast)

        float2 lo = *reinterpret_cast<const float2*>(ap + s0);       // ap[s0..s0+1]
        float2 hi = *reinterpret_cast<const float2*>(ap + s0 + 2);   // ap[s0+2..s0+3]

        // even s0: a1=alpha(s0)=hi.x, a2=alpha(s0-1)=lo.y
        float m0 = fmaxf(hi.x, lo.y);
        float r0 = m0 + lg2(ex2(hi.x - m0) + ex2(lo.y - m0)) + lpB;

        // odd s1=s0+1: a1=alpha(s1)=hi.y, a2=alpha(s0)=hi.x, a3=alpha(s1-2)=lo.y
        float a3 = skA ? lo.y : NEGV;
        float m1 = fmaxf(fmaxf(hi.y, hi.x), a3);
        float sm1 = ex2(hi.y - m1) + ex2(hi.x - m1) + ex2(a3 - m1);
        float r1 = m1 + lg2(sm1) + lpA;

        *reinterpret_cast<float2*>(an + s0 + 2) = make_float2(r0, r1);

        if (has2) {    // s=512: even blank, a1=ap[514], a2=ap[513]
            float b1 = ap[514], b2 = ap[513];
            float m = fmaxf(b1, b2);
            an[514] = m + lg2(ex2(b1 - m) + ex2(b2 - m)) + lpB;
        }

        rs = (rs == 4) ? 0 : rs + 1;
        cur ^= 1;
    }

    asm volatile("cp.async.wait_all;");
    __syncthreads();

    if (tid == 0) {
        int last = 2 * tl;
        float a = abuf[cur][last + 2];
        float c = abuf[cur][last + 1];
        float m = fmaxf(a, c);
        float lae2 = m + lg2(ex2(a - m) + ex2(c - m));
        float lo2 = -lae2 * LN2;
        if (!(lo2 < 1e10f)) lo2 = 0.0f;          // zero_infinity
        g_loss[b] = lo2 / (float)tl;
    }
}

// ---------------------------------------------------------------------------
// Kernel 3: deterministic mean over batch
// ---------------------------------------------------------------------------
__global__ void k_reduce(float* out) {
    float v = (threadIdx.x < B_) ? g_loss[threadIdx.x] : 0.0f;
#pragma unroll
    for (int o = 16; o; o >>= 1) v += __shfl_xor_sync(0xffffffffu, v, o);
    if (threadIdx.x == 0) out[0] = v / (float)B_;
}

// ---------------------------------------------------------------------------
extern "C" void kernel_launch(void* const* d_in, const int* in_sizes, int n_in,
                              void* d_out, int out_size) {
    const float* pred = (const float*)d_in[0];
    const int*   plen = (const int*)d_in[1];
    const int*   gt   = (const int*)d_in[2];
    const int*   glen = (const int*)d_in[3];

    k_lp<<<(B_ * T_) / 4, 128>>>(pred);
    k_dp<<<B_, 256>>>(plen, gt, glen);
    k_reduce<<<1, 32>>>((float*)d_out);
}